// round 17
// baseline (speedup 1.0000x reference)
#include <cuda_runtime.h>
#include <math.h>

// HorizonReward — R17: R16 winner + three chain cuts.
//   - radix-8/4 two-stage policy reduction (2 dependent SHFL latencies, not 3)
//   - Cholesky head (rr0, S00', S20', a22 partial) hoisted into pre-u region
//     (c00/c20/c22 are u-independent)
//   - pairwise-tree moment sums (p11/p33, p13, p21/p32)
// Core structure (verified R14/R16): 32-lane single-chain packed policy,
// affine-l bases, parallel shfl gather moments, analytic linear-coordinate
// covariance, x5-prescaled Cholesky, unroll 2.

typedef unsigned long long u64;

__device__ __forceinline__ u64 pk(float lo, float hi) {
    u64 r; asm("mov.b64 %0,{%1,%2};" : "=l"(r) : "f"(lo), "f"(hi)); return r;
}
__device__ __forceinline__ void upk(u64 a, float& x, float& y) {
    asm("mov.b64 {%0,%1},%2;" : "=f"(x), "=f"(y) : "l"(a));
}
__device__ __forceinline__ u64 sp2(float s) { return pk(s, s); }
__device__ __forceinline__ u64 fma2_(u64 a, u64 b, u64 c) {
    u64 d; asm("fma.rn.f32x2 %0,%1,%2,%3;" : "=l"(d) : "l"(a), "l"(b), "l"(c)); return d;
}
__device__ __forceinline__ u64 mul2_(u64 a, u64 b) {
    u64 d; asm("mul.rn.f32x2 %0,%1,%2;" : "=l"(d) : "l"(a), "l"(b)); return d;
}
__device__ __forceinline__ u64 add2_(u64 a, u64 b) {
    u64 d; asm("add.rn.f32x2 %0,%1,%2;" : "=l"(d) : "l"(a), "l"(b)); return d;
}
__device__ __forceinline__ float rcp_(float x) {
    float r; asm("rcp.approx.f32 %0,%1;" : "=f"(r) : "f"(x)); return r;
}
__device__ __forceinline__ float ex2_(float x) {
    float r; asm("ex2.approx.f32 %0,%1;" : "=f"(r) : "f"(x)); return r;
}
// two-stage radix-8 / radix-4 32-lane reduction; xor-group pairing keeps
// the fp addition order consistent across lanes (warp-uniform result).
__device__ __forceinline__ float red32_r84(float x) {
    const float a1 = __shfl_xor_sync(0xffffffffu, x, 1);
    const float a2 = __shfl_xor_sync(0xffffffffu, x, 2);
    const float a3 = __shfl_xor_sync(0xffffffffu, x, 3);
    const float a4 = __shfl_xor_sync(0xffffffffu, x, 4);
    const float a5 = __shfl_xor_sync(0xffffffffu, x, 5);
    const float a6 = __shfl_xor_sync(0xffffffffu, x, 6);
    const float a7 = __shfl_xor_sync(0xffffffffu, x, 7);
    x = ((x + a1) + (a2 + a3)) + ((a4 + a5) + (a6 + a7));
    const float b1 = __shfl_xor_sync(0xffffffffu, x, 8);
    const float b2 = __shfl_xor_sync(0xffffffffu, x, 16);
    const float b3 = __shfl_xor_sync(0xffffffffu, x, 24);
    return (x + b1) + (b2 + b3);
}

#define DTc      0.05f
#define K1c      (0.05f / 1.1f)
#define K3c      (0.5f * (4.0f / 3.0f))
#define K2c      (0.5f * 0.1f / 1.1f)
#define INV11c   (1.0f / 1.1f)
#define DIAG5c   (5.0f * (0.01f * 0.05f + 2.0f * 1e-6f))

__global__ __launch_bounds__(32, 1)
void horizon_reward_kernel(const float* __restrict__ p, float* __restrict__ out)
{
    const int lane = threadIdx.x & 31;

    // ---- policy params: ONE packed chain per lane (RBFs lane, lane+32) ----
    u64 nmu[4], L[10];
    float w0p, w1p;
    {
        const int a0 = lane, a1 = lane + 32;
        const bool hb = (a1 < 50);
        w0p = p[a0]; w1p = hb ? p[a1] : 0.f;
        #pragma unroll
        for (int k = 0; k < 4; ++k)
            nmu[k] = pk(-p[50 + k * 50 + a0], hb ? -p[50 + k * 50 + a1] : 0.f);
        #pragma unroll
        for (int t = 0; t < 10; ++t)
            L[t] = pk(p[250 + a0 * 10 + t], hb ? p[250 + a1 * 10 + t] : 0.f);
    }

    const u64 NL2E2 = sp2(-1.4426950408889634f);
    const u64 NM1_2 = sp2(-1.f);
    const u64 W0_2 = sp2(0.2f), WI_2 = sp2(0.1f), HALF2 = sp2(0.5f);

    // ---- sigma-point roles: lanes 0-8 own points; 9-31 harmless center ----
    const int pt = lane;
    const int col = (pt == 0) ? 3 : ((pt - 1) & 3);
    const float sgn = (pt >= 1 && pt <= 4) ? 1.f : ((pt >= 5 && pt <= 8) ? -1.f : 0.f);
    const bool isC0 = (col == 0), isC1 = (col == 1), isC2 = (col == 2);

    // ---- state (warp-uniform) ----
    float m0 = 0.f, m1 = 0.f, m2 = 0.1f, m3 = 0.f;
    const float r0i = 2.23606797749979f * 1e-3f;
    float S00 = r0i, S10 = 0.f, S20 = 0.f, S30 = 0.f;
    float S11 = r0i, S21 = 0.f, S31 = 0.f;
    float S22 = r0i, S32 = 0.f;
    float S33 = r0i;

    // ---- initial u = policy(m) ----
    float u;
    {
        u64 d0 = add2_(sp2(m0), nmu[0]), d1 = add2_(sp2(m1), nmu[1]);
        u64 d2 = add2_(sp2(m2), nmu[2]), d3 = add2_(sp2(m3), nmu[3]);
        u64 l0 = mul2_(L[0], d0);
        l0 = fma2_(L[4], d1, l0); l0 = fma2_(L[5], d2, l0); l0 = fma2_(L[7], d3, l0);
        u64 l1 = mul2_(L[1], d1); l1 = fma2_(L[6], d2, l1); l1 = fma2_(L[8], d3, l1);
        u64 l2 = mul2_(L[2], d2); l2 = fma2_(L[9], d3, l2);
        u64 l3 = mul2_(L[3], d3);
        u64 q = fma2_(l1, l1, mul2_(l0, l0));
        q = add2_(q, fma2_(l3, l3, mul2_(l2, l2)));
        q = mul2_(q, NL2E2);
        float qa, qb; upk(q, qa, qb);
        float acc = fmaf(w0p, ex2_(qa), w1p * ex2_(qb));
        acc = red32_r84(acc);
        u = fminf(fmaxf(acc, -10.f), 10.f);
    }

    float reward = 0.f;

    #pragma unroll 2
    for (int t = 0; t < 60; ++t) {
        // ======== S-dependent pre-u work ========
        const float r1 = sgn * (isC0 ? S10 : (isC1 ? S11 : 0.f));
        const float r2 = sgn * (isC0 ? S20 : (isC1 ? S21 : (isC2 ? S22 : 0.f)));
        const float r3 = sgn * (isC0 ? S30 : (isC1 ? S31 : (isC2 ? S32 : S33)));

        const float th = m2 + r2, thd = m3 + r3;
        const float s = __sinf(th), c = __cosf(th);
        const float rd = rcp_(fmaf(-K2c * c, c, K3c));
        const float tks = ((thd * thd) * K1c) * s;
        const float g98 = 9.8f * s;

        const float n0 = fmaf(DTc, m1, m0);
        const float n2 = fmaf(DTc, m3, m2);

        // analytic linear-coordinate covariance entries (exact)
        const float A0 = fmaf(DTc, S10, S00);
        const float A1v = DTc * S11;
        const float C0 = fmaf(DTc, S30, S20);
        const float C1 = fmaf(DTc, S31, S21);
        const float C2v = fmaf(DTc, S32, S22);
        const float C3 = DTc * S33;
        const float c00 = fmaf(A1v, A1v, A0 * A0) + DIAG5c;
        const float c20 = fmaf(A1v, C1, A0 * C0);
        const float c22 = fmaf(C3, C3, fmaf(C2v, C2v, fmaf(C1, C1, C0 * C0))) + DIAG5c;
        const u64 A0h2 = sp2(0.5f * A0), A1h2 = sp2(0.5f * A1v);
        const u64 C0h2 = sp2(0.5f * C0), C1h2 = sp2(0.5f * C1);
        const u64 C2h2 = sp2(0.5f * C2v), C3h2 = sp2(0.5f * C3);

        // ---- Cholesky head (u-independent): rr0, new S00/S20, a22 partial ----
        const float rr0 = rsqrtf(c00);
        const float nS00 = c00 * rr0;
        const float nS20 = c20 * rr0;
        const float a22p = fmaf(-nS20, nS20, c22);

        // ---- policy l-vector BASES at (n0, m1, n2, m3) ----
        const u64 a0c = add2_(sp2(n0), nmu[0]), a1m = add2_(sp2(m1), nmu[1]);
        const u64 a2c = add2_(sp2(n2), nmu[2]), a3m = add2_(sp2(m3), nmu[3]);
        u64 l0b = mul2_(L[0], a0c);
        l0b = fma2_(L[4], a1m, l0b); l0b = fma2_(L[5], a2c, l0b); l0b = fma2_(L[7], a3m, l0b);
        u64 l1b = mul2_(L[1], a1m); l1b = fma2_(L[6], a2c, l1b); l1b = fma2_(L[8], a3m, l1b);
        u64 l2b = mul2_(L[2], a2c); l2b = fma2_(L[9], a3m, l2b);
        u64 l3b = mul2_(L[3], a3m);

        // ================== u arrives: short post-u chain ====================
        const float ud = u * INV11c;
        const float temp = tks + ud;
        const float num = fmaf(-c, temp, g98);
        const float ta = num * rd;
        const float xa = fmaf(-K1c, ta * c, temp);
        const float y1 = fmaf(DTc, xa, r1);      // next1 - m1 (uncentered)
        const float y3 = fmaf(DTc, ta, r3);      // next3 - m3 (uncentered)

        // ---- gather all 9 (y1,y3): 18 parallel shfl.idx; keep scalars live ----
        float g1[9], g3[9];
        u64 z[9];
        #pragma unroll
        for (int j = 0; j < 9; ++j) {
            g1[j] = __shfl_sync(0xffffffffu, y1, j);
            g3[j] = __shfl_sync(0xffffffffu, y3, j);
            z[j] = pk(g1[j], g3[j]);
        }

        // ---- packed means ----
        const u64 sA = add2_(add2_(z[1], z[2]), add2_(z[3], z[4]));
        const u64 sB = add2_(add2_(z[5], z[6]), add2_(z[7], z[8]));
        const u64 d13 = fma2_(WI_2, add2_(sA, sB), mul2_(W0_2, z[0]));
        float d1, d3; upk(d13, d1, d3);

        // ---- policy fixup + reduce -> u_{t+1} ----
        {
            const u64 d1_2 = sp2(d1), d3_2 = sp2(d3);
            u64 l0 = fma2_(L[4], d1_2, fma2_(L[7], d3_2, l0b));
            u64 l1 = fma2_(L[1], d1_2, fma2_(L[8], d3_2, l1b));
            u64 l2 = fma2_(L[9], d3_2, l2b);
            u64 l3 = fma2_(L[3], d3_2, l3b);
            u64 q = fma2_(l1, l1, mul2_(l0, l0));
            q = add2_(q, fma2_(l3, l3, mul2_(l2, l2)));
            q = mul2_(q, NL2E2);
            float qa, qb; upk(q, qa, qb);
            float acc = fmaf(w0p, ex2_(qa), w1p * ex2_(qb));
            acc = red32_r84(acc);
            u = fminf(fmaxf(acc, -10.f), 10.f);
        }

        // ---- moments from gathered z (off the u-path), pairwise trees ----
        const u64 gz1 = fma2_(z[5], NM1_2, z[1]);
        const u64 gz2 = fma2_(z[6], NM1_2, z[2]);
        const u64 gz3 = fma2_(z[7], NM1_2, z[3]);
        const u64 gz4 = fma2_(z[8], NM1_2, z[4]);
        const u64 p1030 = fma2_(A1h2, gz2, mul2_(A0h2, gz1));
        const u64 tA = fma2_(C1h2, gz2, mul2_(C0h2, gz1));
        const u64 tB = fma2_(C3h2, gz4, mul2_(C2h2, gz3));
        const u64 p2132 = add2_(tA, tB);
        float p10, p30, p21, p32;
        upk(p1030, p10, p30); upk(p2132, p21, p32);

        const u64 s12 = fma2_(z[2], z[2], mul2_(z[1], z[1]));
        const u64 s34 = fma2_(z[4], z[4], mul2_(z[3], z[3]));
        const u64 s56 = fma2_(z[6], z[6], mul2_(z[5], z[5]));
        const u64 s78 = fma2_(z[8], z[8], mul2_(z[7], z[7]));
        const u64 sq = add2_(add2_(s12, s34), add2_(s56, s78));
        const u64 p1133 = fma2_(HALF2, sq, mul2_(z[0], z[0]));
        float p11, p33; upk(p1133, p11, p33);

        const float t12 = fmaf(g1[2], g3[2], g1[1] * g3[1]);
        const float t34 = fmaf(g1[4], g3[4], g1[3] * g3[3]);
        const float t56 = fmaf(g1[6], g3[6], g1[5] * g3[5]);
        const float t78 = fmaf(g1[8], g3[8], g1[7] * g3[7]);
        const float xs = (t12 + t34) + (t56 + t78);
        const float p13 = fmaf(0.5f, xs, g1[0] * g3[0]);

        // ---- de-meaned covariance + next mean ----
        const float n1 = m1 + d1;
        const float n3 = m3 + d3;
        const float f1 = 5.f * d1, f3 = 5.f * d3;
        const float c11 = fmaf(-f1, d1, p11) + DIAG5c;
        const float c31 = fmaf(-f1, d3, p13);
        const float c33 = fmaf(-f3, d3, p33) + DIAG5c;
        const float c10 = p10, c30 = p30, c21 = p21, c32 = p32;

        // ---- reward: n^T Q n + 0.2 * trace(Q * 5C) ----
        const float q = fmaf(n0, n0, fmaf(n1, n1, fmaf(10.f * n2, n2, n3 * n3)));
        const float tr = c00 + c11 + fmaf(10.f, c22, c33);
        reward -= fmaf(0.2f, tr, q);

        // ---- 4x4 Cholesky tail (head hoisted above) ----
        S00 = nS00; S20 = nS20;
        S10 = c10 * rr0; S30 = c30 * rr0;
        const float a11 = fmaf(-S10, S10, c11);
        const float rr1 = rsqrtf(a11);
        S11 = a11 * rr1;
        S21 = fmaf(-S20, S10, c21) * rr1;
        S31 = fmaf(-S30, S10, c31) * rr1;
        const float a22 = fmaf(-S21, S21, a22p);
        const float rr2 = rsqrtf(a22);
        S22 = a22 * rr2;
        S32 = fmaf(-S31, S21, fmaf(-S30, S20, c32)) * rr2;
        const float a33 = fmaf(-S32, S32, fmaf(-S31, S31, fmaf(-S30, S30, c33)));
        S33 = a33 * rsqrtf(a33);

        m0 = n0; m1 = n1; m2 = n2; m3 = n3;
    }

    if (lane == 0) out[0] = reward;
}

extern "C" void kernel_launch(void* const* d_in, const int* in_sizes, int n_in,
                              void* d_out, int out_size) {
    (void)in_sizes; (void)n_in; (void)out_size;
    horizon_reward_kernel<<<1, 32>>>((const float*)d_in[0], (float*)d_out);
}